// round 12
// baseline (speedup 1.0000x reference)
#include <cuda_runtime.h>
#include <cuda_fp16.h>
#include <math.h>

#define EMBED 1024
#define HEAD  128
#define BATCH 8
#define SEQ   2048
#define MTOT  (BATCH*SEQ)
#define VTROWS 136                      // 128 V rows + ones row + 7 zero rows

#define QK_SCALE 0.045084295033136845f  // log2(e) / sqrt(1024)

// Scratch (allocation-free). All values stored as fp16.
__device__ __half g_q[MTOT * HEAD];             // pre-scaled by log2(e)/32
__device__ __half g_k[MTOT * HEAD];
__device__ __half g_vt[BATCH * VTROWS * SEQ];   // V^T: [b][h][s], h=128 ones
__device__ __half g_wt[3][HEAD][EMBED];         // W^T fp16: [z][n][k]

// ---------------------------------------------------------------------------
// helpers
// ---------------------------------------------------------------------------
__device__ __forceinline__ unsigned packh2(float a, float b) {
    __half2 h = __floats2half2_rn(a, b);
    return *reinterpret_cast<unsigned*>(&h);
}
__device__ __forceinline__ float ex2f(float x) {
    float y; asm("ex2.approx.f32 %0, %1;" : "=f"(y) : "f"(x)); return y;
}
__device__ __forceinline__ void mma_f16(float d[4],
                                        unsigned a0, unsigned a1, unsigned a2, unsigned a3,
                                        unsigned b0, unsigned b1) {
    asm volatile(
        "mma.sync.aligned.m16n8k16.row.col.f32.f16.f16.f32 "
        "{%0,%1,%2,%3}, {%4,%5,%6,%7}, {%8,%9}, {%0,%1,%2,%3};"
        : "+f"(d[0]), "+f"(d[1]), "+f"(d[2]), "+f"(d[3])
        : "r"(a0), "r"(a1), "r"(a2), "r"(a3), "r"(b0), "r"(b1));
}
__device__ __forceinline__ void ldsm4(unsigned m[4], unsigned saddr) {
    asm volatile("ldmatrix.sync.aligned.m8n8.x4.shared.b16 {%0,%1,%2,%3}, [%4];"
                 : "=r"(m[0]), "=r"(m[1]), "=r"(m[2]), "=r"(m[3]) : "r"(saddr));
}
__device__ __forceinline__ void cpasync16(unsigned dst, const void* src) {
    asm volatile("cp.async.ca.shared.global [%0], [%1], 16;" :: "r"(dst), "l"(src));
}
#define CP_COMMIT asm volatile("cp.async.commit_group;")
#define CP_WAIT0  asm volatile("cp.async.wait_group 0;" ::: "memory")
#define CP_WAIT1  asm volatile("cp.async.wait_group 1;" ::: "memory")

// ---------------------------------------------------------------------------
// Prep 1: transpose + fp16 round of W into g_wt[z][n][k].
// ---------------------------------------------------------------------------
__global__ __launch_bounds__(256) void w_prep(const float* __restrict__ Wq,
                                              const float* __restrict__ Wk,
                                              const float* __restrict__ Wv)
{
    const int z = blockIdx.y;
    const float* W = (z == 0) ? Wq : (z == 1) ? Wk : Wv;
    const int n = blockIdx.x;
    const int k = threadIdx.x * 4;
    float a = W[(size_t)(k + 0) * HEAD + n];
    float b = W[(size_t)(k + 1) * HEAD + n];
    float c = W[(size_t)(k + 2) * HEAD + n];
    float d = W[(size_t)(k + 3) * HEAD + n];
    *reinterpret_cast<uint2*>(&g_wt[z][n][k]) =
        make_uint2(packh2(a, b), packh2(c, d));
}

// ---------------------------------------------------------------------------
// Prep 2: fill g_vt rows 128..135: row 128 = 1.0 (ones column for row-sums),
// rows 129..135 = 0.   8 b x 8 h x 2048 s = 32768 uint2 stores.
// ---------------------------------------------------------------------------
__global__ __launch_bounds__(256) void vt_ones()
{
    int j = blockIdx.x * 256 + threadIdx.x;        // 0..32767
    int b = j >> 12;
    int rem = j & 4095;
    int hh = rem >> 9;                             // 0..7
    int s4 = (rem & 511) * 4;
    unsigned v = (hh == 0) ? packh2(1.f, 1.f) : 0u;
    *reinterpret_cast<uint2*>(
        &g_vt[((size_t)b * VTROWS + 128 + hh) * SEQ + s4]) = make_uint2(v, v);
}

// ---------------------------------------------------------------------------
// Kernel A: FUSED QKV projection (fp16 mma), double-buffered.  (unchanged R10)
// ---------------------------------------------------------------------------
#define FXS_H (64 * 40)
#define FWS_H (384 * 40)
__global__ __launch_bounds__(384, 1) void qkv_fused(const float* __restrict__ x)
{
    __shared__ __half smh[2 * FXS_H + 2 * FWS_H];
    __half* Xs[2] = { smh, smh + FXS_H };

    const int tid = threadIdx.x;
    const int wid = tid >> 5, lane = tid & 31;
    const int qi = lane >> 2, qj = lane & 3;
    const int g  = lane >> 3, r = lane & 7;
    const int l16 = lane & 15, hi16 = lane >> 4;
    const int wn = wid % 6, wm = wid / 6;
    const int m0 = blockIdx.x * 64;

    const unsigned SB = (unsigned)__cvta_generic_to_shared(smh);
    const unsigned XsB[2] = { SB, SB + FXS_H * 2 };
    const unsigned WsB[2] = { SB + 2 * FXS_H * 2, SB + 2 * FXS_H * 2 + FWS_H * 2 };
    const __half* wsrc = &g_wt[0][0][0];

    float c[2][8][4];
#pragma unroll
    for (int mt = 0; mt < 2; mt++)
#pragma unroll
        for (int nt = 0; nt < 8; nt++)
#pragma unroll
            for (int e = 0; e < 4; e++) c[mt][nt][e] = 0.f;

    const float* xbase = x + (size_t)m0 * EMBED;

    {
#pragma unroll
        for (int p = 0; p < 4; p++) {
            int i = tid + p * 384;
            int row = i >> 2, c4 = i & 3;
            cpasync16(WsB[0] + (unsigned)(row * 80 + c4 * 16),
                      wsrc + (size_t)row * EMBED + c4 * 8);
        }
        CP_COMMIT;
        if (tid < 256) {
#pragma unroll
            for (int p = 0; p < 2; p++) {
                int i = tid + p * 256;
                int row = i >> 3, c4 = i & 7;
                float4 v = *reinterpret_cast<const float4*>(
                    &xbase[(size_t)row * EMBED + c4 * 4]);
                *reinterpret_cast<uint2*>(&Xs[0][row * 40 + c4 * 4]) =
                    make_uint2(packh2(v.x, v.y), packh2(v.z, v.w));
            }
        }
    }

    for (int ch = 0; ch < 32; ch++) {
        const int cur = ch & 1, nxt = cur ^ 1;
        CP_WAIT0;
        __syncthreads();

        float4 xr[2];
        if (ch < 31) {
            const int k0n = (ch + 1) * 32;
#pragma unroll
            for (int p = 0; p < 4; p++) {
                int i = tid + p * 384;
                int row = i >> 2, c4 = i & 3;
                cpasync16(WsB[nxt] + (unsigned)(row * 80 + c4 * 16),
                          wsrc + (size_t)row * EMBED + k0n + c4 * 8);
            }
            CP_COMMIT;
            if (tid < 256) {
#pragma unroll
                for (int p = 0; p < 2; p++) {
                    int i = tid + p * 256;
                    int row = i >> 3, c4 = i & 7;
                    xr[p] = *reinterpret_cast<const float4*>(
                        &xbase[(size_t)row * EMBED + k0n + c4 * 4]);
                }
            }
        }

#pragma unroll
        for (int ks = 0; ks < 2; ks++) {
            unsigned a[2][4];
#pragma unroll
            for (int mt = 0; mt < 2; mt++)
                ldsm4(a[mt], XsB[cur] + (unsigned)((wm * 32 + mt * 16 + l16) * 80
                                                   + hi16 * 16 + ks * 32));
#pragma unroll
            for (int np = 0; np < 4; np++) {
                unsigned bm[4];
                ldsm4(bm, WsB[cur] + (unsigned)((wn * 64 + np * 16 + (g >> 1) * 8 + r) * 80
                                                + (g & 1) * 16 + ks * 32));
                mma_f16(c[0][2 * np],     a[0][0], a[0][1], a[0][2], a[0][3], bm[0], bm[1]);
                mma_f16(c[0][2 * np + 1], a[0][0], a[0][1], a[0][2], a[0][3], bm[2], bm[3]);
                mma_f16(c[1][2 * np],     a[1][0], a[1][1], a[1][2], a[1][3], bm[0], bm[1]);
                mma_f16(c[1][2 * np + 1], a[1][0], a[1][1], a[1][2], a[1][3], bm[2], bm[3]);
            }
        }

        if (ch < 31 && tid < 256) {
#pragma unroll
            for (int p = 0; p < 2; p++) {
                int i = tid + p * 256;
                int row = i >> 3, c4 = i & 7;
                *reinterpret_cast<uint2*>(&Xs[nxt][row * 40 + c4 * 4]) =
                    make_uint2(packh2(xr[p].x, xr[p].y), packh2(xr[p].z, xr[p].w));
            }
        }
    }

    // ---- epilogue ----
    if (wn < 4) {
        __half* out = (wn < 2) ? g_q : g_k;
        const float sc = (wn < 2) ? QK_SCALE : 1.0f;
        const int cb = (wn & 1) * 64;
#pragma unroll
        for (int mt = 0; mt < 2; mt++) {
            int r0 = m0 + wm * 32 + mt * 16 + qi;
#pragma unroll
            for (int nt = 0; nt < 8; nt++) {
                int col = cb + nt * 8 + 2 * qj;
                *reinterpret_cast<unsigned*>(&out[(size_t)r0 * HEAD + col]) =
                    packh2(c[mt][nt][0] * sc, c[mt][nt][1] * sc);
                *reinterpret_cast<unsigned*>(&out[(size_t)(r0 + 8) * HEAD + col]) =
                    packh2(c[mt][nt][2] * sc, c[mt][nt][3] * sc);
            }
        }
    }
    __syncthreads();
    __half* T = smh;                 // [h=128][s=64], stride 72 halves
    if (wn >= 4) {
#pragma unroll
        for (int mt = 0; mt < 2; mt++) {
            int srow = wm * 32 + mt * 16 + qi;
#pragma unroll
            for (int nt = 0; nt < 8; nt++) {
                int h = (wn - 4) * 64 + nt * 8 + 2 * qj;
                T[h * 72 + srow]           = __float2half_rn(c[mt][nt][0]);
                T[(h + 1) * 72 + srow]     = __float2half_rn(c[mt][nt][1]);
                T[h * 72 + srow + 8]       = __float2half_rn(c[mt][nt][2]);
                T[(h + 1) * 72 + srow + 8] = __float2half_rn(c[mt][nt][3]);
            }
        }
    }
    __syncthreads();
    {
        const int b = m0 >> 11, s0 = m0 & 2047;
        if (tid < 256) {
#pragma unroll
            for (int p = 0; p < 8; p++) {
                int i = tid + p * 256;
                int h = i >> 4, cc = i & 15;
                uint2 v = *reinterpret_cast<const uint2*>(&T[h * 72 + cc * 4]);
                *reinterpret_cast<uint2*>(
                    &g_vt[((size_t)b * VTROWS + h) * SEQ + s0 + cc * 4]) = v;
            }
        }
    }
}

// ---------------------------------------------------------------------------
// Kernel B: flash attention (fp16 mma), BN=64, pipelined cp.async.
// P stays in registers (QK C-frag == PV A-frag layout). Row-sum l via a
// ones-column appended to V (h=128). exp via raw ex2.approx.f32.
// ---------------------------------------------------------------------------
#define KS_H (64 * 136)
#define VT_H (144 * 72)          // 136 staged rows + 8 pad rows for ldsm np=8
#define FA_SMEM ((KS_H + VT_H) * 2)   // 38144 B

__global__ __launch_bounds__(128, 2) void flash_mma(float* __restrict__ out)
{
    extern __shared__ __half smf[];
    const unsigned SB = (unsigned)__cvta_generic_to_shared(smf);
    const unsigned KsB = SB;
    const unsigned VtB = SB + KS_H * 2;

    const int tid = threadIdx.x;
    const int wid = tid >> 5, lane = tid & 31;
    const int qi = lane >> 2, qj = lane & 3;
    const int g  = lane >> 3, r = lane & 7;
    const int l16 = lane & 15, hi16 = lane >> 4;

    const int bid = blockIdx.x;
    const int t  = (bid < 148) ? bid : 403 - bid;
    const int qt = 31 - (t >> 3);
    const int b  = t & 7;
    const int q0 = qt * 64;
    const int m0 = wid * 16;

    const __half* kbase  = g_k  + (size_t)b * SEQ * HEAD;
    const __half* vtbase = g_vt + (size_t)b * VTROWS * SEQ;

    // ---- stage Q through Ks, ldmatrix into regs ----
    {
        const __half* qb = g_q + ((size_t)b * SEQ + q0) * HEAD;
#pragma unroll
        for (int p = 0; p < 8; p++) {
            int i = tid + p * 128;
            int row = i >> 4, c4 = i & 15;
            cpasync16(KsB + (unsigned)(row * 272 + c4 * 16), qb + (size_t)row * HEAD + c4 * 8);
        }
        CP_COMMIT; CP_WAIT0;
        __syncthreads();
    }
    unsigned qa[8][4];
    {
        const unsigned aOff = (unsigned)((m0 + l16) * 272 + hi16 * 16);
#pragma unroll
        for (int ks = 0; ks < 8; ks++) ldsm4(qa[ks], KsB + aOff + ks * 32);
    }
    __syncthreads();

    // prologue: issue K(0) then V(0) (136 rows incl. ones row)
#pragma unroll
    for (int p = 0; p < 8; p++) {
        int i = tid + p * 128;
        int row = i >> 4, c4 = i & 15;
        cpasync16(KsB + (unsigned)(row * 272 + c4 * 16), kbase + (size_t)row * HEAD + c4 * 8);
    }
    CP_COMMIT;
#pragma unroll
    for (int p = 0; p < 9; p++) {
        int i = tid + p * 128;
        if (i < 1088) {
            int h = i >> 3, c4 = i & 7;
            cpasync16(VtB + (unsigned)(h * 144 + c4 * 16), vtbase + (size_t)h * SEQ + c4 * 8);
        }
    }
    CP_COMMIT;

    // o tiles: 0..15 = HEAD, 16 = l (ones col), 17 = pad garbage (unused)
    float o[18][4];
#pragma unroll
    for (int nt = 0; nt < 18; nt++)
#pragma unroll
        for (int e = 0; e < 4; e++) o[nt][e] = 0.f;
    float mx0 = -INFINITY, mx1 = -INFINITY;

    const int r0g = q0 + m0 + qi;
    const int r1g = r0g + 8;

    const unsigned bOff = (unsigned)(((g >> 1) * 8 + r) * 272 + (g & 1) * 16);
    const unsigned vOff = (unsigned)(((g >> 1) * 8 + r) * 144 + (g & 1) * 16);

    for (int kt = 0; kt <= qt; kt++) {
        CP_WAIT1;            // K(kt) landed (V(kt) may still fly)
        __syncthreads();

        // ---- S = Q K^T ----
        float s[8][4];
#pragma unroll
        for (int nt = 0; nt < 8; nt++)
#pragma unroll
            for (int e = 0; e < 4; e++) s[nt][e] = 0.f;
#pragma unroll
        for (int ks = 0; ks < 8; ks++) {
#pragma unroll
            for (int np = 0; np < 4; np++) {
                unsigned bm[4];
                ldsm4(bm, KsB + bOff + (unsigned)(np * 4352 + ks * 32));
                mma_f16(s[2 * np],     qa[ks][0], qa[ks][1], qa[ks][2], qa[ks][3], bm[0], bm[1]);
                mma_f16(s[2 * np + 1], qa[ks][0], qa[ks][1], qa[ks][2], qa[ks][3], bm[2], bm[3]);
            }
        }
        __syncthreads();

        // issue K(kt+1)
        if (kt < qt) {
            const __half* kb = kbase + (size_t)(kt + 1) * 64 * HEAD;
#pragma unroll
            for (int p = 0; p < 8; p++) {
                int i = tid + p * 128;
                int row = i >> 4, c4 = i & 15;
                cpasync16(KsB + (unsigned)(row * 272 + c4 * 16),
                          kb + (size_t)row * HEAD + c4 * 8);
            }
        }
        CP_COMMIT;

        // causal mask on the diagonal tile
        if (kt == qt) {
#pragma unroll
            for (int nt = 0; nt < 8; nt++) {
                int cb = kt * 64 + nt * 8 + 2 * qj;
                if (cb > r0g)     s[nt][0] = -INFINITY;
                if (cb + 1 > r0g) s[nt][1] = -INFINITY;
                if (cb > r1g)     s[nt][2] = -INFINITY;
                if (cb + 1 > r1g) s[nt][3] = -INFINITY;
            }
        }

        // ---- online softmax: P packed straight into PV A-frag registers ----
        unsigned pp0[8], pp1[8];
        {
            float t0 = -INFINITY, t1 = -INFINITY;
#pragma unroll
            for (int nt = 0; nt < 8; nt++) {
                t0 = fmaxf(t0, fmaxf(s[nt][0], s[nt][1]));
                t1 = fmaxf(t1, fmaxf(s[nt][2], s[nt][3]));
            }
            t0 = fmaxf(t0, __shfl_xor_sync(0xffffffffu, t0, 1));
            t0 = fmaxf(t0, __shfl_xor_sync(0xffffffffu, t0, 2));
            t1 = fmaxf(t1, __shfl_xor_sync(0xffffffffu, t1, 1));
            t1 = fmaxf(t1, __shfl_xor_sync(0xffffffffu, t1, 2));

            float mn0 = fmaxf(mx0, t0), mn1 = fmaxf(mx1, t1);
            float cr0 = ex2f(mx0 - mn0), cr1 = ex2f(mx1 - mn1);
            mx0 = mn0; mx1 = mn1;

#pragma unroll
            for (int nt = 0; nt < 8; nt++) {
                pp0[nt] = packh2(ex2f(s[nt][0] - mn0), ex2f(s[nt][1] - mn0));
                pp1[nt] = packh2(ex2f(s[nt][2] - mn1), ex2f(s[nt][3] - mn1));
            }

            if (__any_sync(0xffffffffu, (cr0 < 1.f) || (cr1 < 1.f))) {
#pragma unroll
                for (int nt = 0; nt < 17; nt++) {
                    o[nt][0] *= cr0; o[nt][1] *= cr0;
                    o[nt][2] *= cr1; o[nt][3] *= cr1;
                }
            }
        }

        CP_WAIT1;            // V(kt) landed
        __syncthreads();

        // ---- O += P V : A from registers, 4 k16 steps x 9 n-pairs ----
#pragma unroll
        for (int ks = 0; ks < 4; ks++) {
            unsigned a0 = pp0[2 * ks], a1 = pp1[2 * ks];
            unsigned a2 = pp0[2 * ks + 1], a3 = pp1[2 * ks + 1];
#pragma unroll
            for (int np = 0; np < 9; np++) {
                unsigned bm[4];
                ldsm4(bm, VtB + vOff + (unsigned)(np * 2304 + ks * 32));
                mma_f16(o[2 * np],     a0, a1, a2, a3, bm[0], bm[1]);
                mma_f16(o[2 * np + 1], a0, a1, a2, a3, bm[2], bm[3]);
            }
        }
        __syncthreads();

        // issue V(kt+1)
        if (kt < qt) {
            const __half* vb = vtbase + (size_t)(kt + 1) * 64;
#pragma unroll
            for (int p = 0; p < 9; p++) {
                int i = tid + p * 128;
                if (i < 1088) {
                    int h = i >> 3, c4 = i & 7;
                    cpasync16(VtB + (unsigned)(h * 144 + c4 * 16),
                              vb + (size_t)h * SEQ + c4 * 8);
                }
            }
        }
        CP_COMMIT;
    }

    // epilogue: l lives in o[16][0]/o[16][2] of the qj==0 lane of each quad
    {
        float l0 = __shfl_sync(0xffffffffu, o[16][0], lane & 28);
        float l1 = __shfl_sync(0xffffffffu, o[16][2], lane & 28);
        float inv0 = 1.f / l0, inv1 = 1.f / l1;
        float* ob = out + ((size_t)b * SEQ) * HEAD;
#pragma unroll
        for (int nt = 0; nt < 16; nt++) {
            int col = nt * 8 + 2 * qj;
            *reinterpret_cast<float2*>(&ob[(size_t)r0g * HEAD + col]) =
                make_float2(o[nt][0] * inv0, o[nt][1] * inv0);
            *reinterpret_cast<float2*>(&ob[(size_t)r1g * HEAD + col]) =
                make_float2(o[nt][2] * inv1, o[nt][3] * inv1);
        }
    }
}

// ---------------------------------------------------------------------------
extern "C" void kernel_launch(void* const* d_in, const int* in_sizes, int n_in,
                              void* d_out, int out_size)
{
    const float* x  = (const float*)d_in[0];
    const float* Wk = (const float*)d_in[1];
    const float* Wq = (const float*)d_in[2];
    const float* Wv = (const float*)d_in[3];
    float* out = (float*)d_out;

    w_prep<<<dim3(HEAD, 3), 256>>>(Wq, Wk, Wv);
    vt_ones<<<128, 256>>>();
    qkv_fused<<<MTOT / 64, 384>>>(x);

    cudaFuncSetAttribute(flash_mma, cudaFuncAttributeMaxDynamicSharedMemorySize, FA_SMEM);
    flash_mma<<<dim3(256, 1), 128, FA_SMEM>>>(out);
}

// round 14
// speedup vs baseline: 1.1247x; 1.1247x over previous
#include <cuda_runtime.h>
#include <cuda_fp16.h>
#include <math.h>

#define EMBED 1024
#define HEAD  128
#define BATCH 8
#define SEQ   2048
#define MTOT  (BATCH*SEQ)
#define VTROWS 136                      // 128 V rows + ones row + 7 zero rows

#define QK_SCALE 0.045084295033136845f  // log2(e) / sqrt(1024)

// Scratch (allocation-free). All values stored as fp16.
__device__ __half g_q[MTOT * HEAD];             // pre-scaled by log2(e)/32
__device__ __half g_k[MTOT * HEAD];
__device__ __half g_vt[BATCH * VTROWS * SEQ];   // V^T: [b][h][s], h=128 ones
__device__ __half g_wt[3][HEAD][EMBED];         // W^T fp16: [z][n][k]

// ---------------------------------------------------------------------------
// helpers
// ---------------------------------------------------------------------------
__device__ __forceinline__ unsigned packh2(float a, float b) {
    __half2 h = __floats2half2_rn(a, b);
    return *reinterpret_cast<unsigned*>(&h);
}
__device__ __forceinline__ float ex2f(float x) {
    float y; asm("ex2.approx.f32 %0, %1;" : "=f"(y) : "f"(x)); return y;
}
__device__ __forceinline__ void mma_f16(float d[4],
                                        unsigned a0, unsigned a1, unsigned a2, unsigned a3,
                                        unsigned b0, unsigned b1) {
    asm volatile(
        "mma.sync.aligned.m16n8k16.row.col.f32.f16.f16.f32 "
        "{%0,%1,%2,%3}, {%4,%5,%6,%7}, {%8,%9}, {%0,%1,%2,%3};"
        : "+f"(d[0]), "+f"(d[1]), "+f"(d[2]), "+f"(d[3])
        : "r"(a0), "r"(a1), "r"(a2), "r"(a3), "r"(b0), "r"(b1));
}
__device__ __forceinline__ void ldsm4(unsigned m[4], unsigned saddr) {
    asm volatile("ldmatrix.sync.aligned.m8n8.x4.shared.b16 {%0,%1,%2,%3}, [%4];"
                 : "=r"(m[0]), "=r"(m[1]), "=r"(m[2]), "=r"(m[3]) : "r"(saddr));
}
__device__ __forceinline__ void cpasync16(unsigned dst, const void* src) {
    asm volatile("cp.async.ca.shared.global [%0], [%1], 16;" :: "r"(dst), "l"(src));
}
#define CP_COMMIT asm volatile("cp.async.commit_group;")
#define CP_WAIT0  asm volatile("cp.async.wait_group 0;" ::: "memory")
#define CP_WAIT1  asm volatile("cp.async.wait_group 1;" ::: "memory")

// ---------------------------------------------------------------------------
// Prep 1: transpose + fp16 round of W into g_wt[z][n][k].
// ---------------------------------------------------------------------------
__global__ __launch_bounds__(256) void w_prep(const float* __restrict__ Wq,
                                              const float* __restrict__ Wk,
                                              const float* __restrict__ Wv)
{
    const int z = blockIdx.y;
    const float* W = (z == 0) ? Wq : (z == 1) ? Wk : Wv;
    const int n = blockIdx.x;
    const int k = threadIdx.x * 4;
    float a = W[(size_t)(k + 0) * HEAD + n];
    float b = W[(size_t)(k + 1) * HEAD + n];
    float c = W[(size_t)(k + 2) * HEAD + n];
    float d = W[(size_t)(k + 3) * HEAD + n];
    *reinterpret_cast<uint2*>(&g_wt[z][n][k]) =
        make_uint2(packh2(a, b), packh2(c, d));
}

// ---------------------------------------------------------------------------
// Prep 2: fill g_vt rows 128..135 (ones row + zero pad).
// ---------------------------------------------------------------------------
__global__ __launch_bounds__(256) void vt_ones()
{
    int j = blockIdx.x * 256 + threadIdx.x;
    int b = j >> 12;
    int rem = j & 4095;
    int hh = rem >> 9;
    int s4 = (rem & 511) * 4;
    unsigned v = (hh == 0) ? packh2(1.f, 1.f) : 0u;
    *reinterpret_cast<uint2*>(
        &g_vt[((size_t)b * VTROWS + 128 + hh) * SEQ + s4]) = make_uint2(v, v);
}

// ---------------------------------------------------------------------------
// Kernel A: FUSED QKV projection (fp16 mma), TRIPLE-buffered.
// CTA = 64 rows x 384 cols (Q|K|V), 384 threads = 12 warps (2m x 6n),
// warp tile m32 x n64. W(ch+2) issued at top of iter ch (buffer freed by the
// iter-ch barrier) -> 2 landing windows per group; wait_group 1 steady state.
// ---------------------------------------------------------------------------
#define FXS_H (64 * 40)      // 2560 halves per X buffer
#define FWS_H (384 * 40)     // 15360 halves per W buffer
#define BUFH  (FXS_H + FWS_H)
#define QKV_SMEM (3 * BUFH * 2)   // 107520 B

__global__ __launch_bounds__(384, 1) void qkv_fused(const float* __restrict__ x)
{
    extern __shared__ __half smh[];

    const int tid = threadIdx.x;
    const int wid = tid >> 5, lane = tid & 31;
    const int qi = lane >> 2, qj = lane & 3;
    const int g  = lane >> 3, r = lane & 7;
    const int l16 = lane & 15, hi16 = lane >> 4;
    const int wn = wid % 6, wm = wid / 6;
    const int m0 = blockIdx.x * 64;

    const unsigned SB = (unsigned)__cvta_generic_to_shared(smh);
    const __half* wsrc = &g_wt[0][0][0];    // flat rows: z*128 + n

    float c[2][8][4];
#pragma unroll
    for (int mt = 0; mt < 2; mt++)
#pragma unroll
        for (int nt = 0; nt < 8; nt++)
#pragma unroll
            for (int e = 0; e < 4; e++) c[mt][nt][e] = 0.f;

    const float* xbase = x + (size_t)m0 * EMBED;

    // prologue: W0,W1 via cp.async (2 groups); X0,X1 direct cvt/STS
#pragma unroll
    for (int b = 0; b < 2; b++) {
        const unsigned WsB = SB + (unsigned)(b * BUFH + FXS_H) * 2;
        const int k0 = b * 32;
#pragma unroll
        for (int p = 0; p < 4; p++) {
            int u = tid + p * 384;
            int n = u >> 2, i = u & 3;
            cpasync16(WsB + (unsigned)(n * 80 + i * 16),
                      wsrc + (size_t)n * EMBED + k0 + i * 8);
        }
        CP_COMMIT;
        if (tid < 256) {
#pragma unroll
            for (int p = 0; p < 2; p++) {
                int u = tid + p * 256;
                int row = u >> 3, c4 = u & 7;
                float4 v = *reinterpret_cast<const float4*>(
                    &xbase[(size_t)row * EMBED + k0 + c4 * 4]);
                *reinterpret_cast<uint2*>(&smh[b * BUFH + row * 40 + c4 * 4]) =
                    make_uint2(packh2(v.x, v.y), packh2(v.z, v.w));
            }
        }
    }

    for (int ch = 0; ch < 32; ch++) {
        const int cur = ch % 3;
        CP_WAIT1;            // W(ch) landed (W(ch+1) may still fly)
        __syncthreads();     // also: mma(ch-1) done by all warps -> buf (ch+2)%3 free

        float4 xr[2];
        const bool hx = (ch + 2 < 32);
        if (hx) {
            const int nb = (ch + 2) % 3;
            const int k0n = (ch + 2) * 32;
            const unsigned WsB = SB + (unsigned)(nb * BUFH + FXS_H) * 2;
#pragma unroll
            for (int p = 0; p < 4; p++) {
                int u = tid + p * 384;
                int n = u >> 2, i = u & 3;
                cpasync16(WsB + (unsigned)(n * 80 + i * 16),
                          wsrc + (size_t)n * EMBED + k0n + i * 8);
            }
            if (tid < 256) {
#pragma unroll
                for (int p = 0; p < 2; p++) {
                    int u = tid + p * 256;
                    int row = u >> 3, c4 = u & 7;
                    xr[p] = *reinterpret_cast<const float4*>(
                        &xbase[(size_t)row * EMBED + k0n + c4 * 4]);
                }
            }
        }
        CP_COMMIT;           // unconditional: keeps group arithmetic

        // compute on buffer cur
        const unsigned XsB = SB + (unsigned)(cur * BUFH) * 2;
        const unsigned WsB = XsB + (unsigned)FXS_H * 2;
#pragma unroll
        for (int ks = 0; ks < 2; ks++) {
            unsigned a[2][4];
#pragma unroll
            for (int mt = 0; mt < 2; mt++)
                ldsm4(a[mt], XsB + (unsigned)((wm * 32 + mt * 16 + l16) * 80
                                              + hi16 * 16 + ks * 32));
#pragma unroll
            for (int np = 0; np < 4; np++) {
                unsigned bm[4];
                ldsm4(bm, WsB + (unsigned)((wn * 64 + np * 16 + (g >> 1) * 8 + r) * 80
                                           + (g & 1) * 16 + ks * 32));
                mma_f16(c[0][2 * np],     a[0][0], a[0][1], a[0][2], a[0][3], bm[0], bm[1]);
                mma_f16(c[0][2 * np + 1], a[0][0], a[0][1], a[0][2], a[0][3], bm[2], bm[3]);
                mma_f16(c[1][2 * np],     a[1][0], a[1][1], a[1][2], a[1][3], bm[0], bm[1]);
                mma_f16(c[1][2 * np + 1], a[1][0], a[1][1], a[1][2], a[1][3], bm[2], bm[3]);
            }
        }

        if (hx && tid < 256) {
            const int nb = (ch + 2) % 3;
#pragma unroll
            for (int p = 0; p < 2; p++) {
                int u = tid + p * 256;
                int row = u >> 3, c4 = u & 7;
                *reinterpret_cast<uint2*>(&smh[nb * BUFH + row * 40 + c4 * 4]) =
                    make_uint2(packh2(xr[p].x, xr[p].y), packh2(xr[p].z, xr[p].w));
            }
        }
    }

    // ---- epilogue (verbatim R10) ----
    if (wn < 4) {
        __half* out = (wn < 2) ? g_q : g_k;
        const float sc = (wn < 2) ? QK_SCALE : 1.0f;
        const int cb = (wn & 1) * 64;
#pragma unroll
        for (int mt = 0; mt < 2; mt++) {
            int r0 = m0 + wm * 32 + mt * 16 + qi;
#pragma unroll
            for (int nt = 0; nt < 8; nt++) {
                int col = cb + nt * 8 + 2 * qj;
                *reinterpret_cast<unsigned*>(&out[(size_t)r0 * HEAD + col]) =
                    packh2(c[mt][nt][0] * sc, c[mt][nt][1] * sc);
                *reinterpret_cast<unsigned*>(&out[(size_t)(r0 + 8) * HEAD + col]) =
                    packh2(c[mt][nt][2] * sc, c[mt][nt][3] * sc);
            }
        }
    }
    __syncthreads();
    __half* T = smh;                 // [h=128][s=64], stride 72 halves
    if (wn >= 4) {
#pragma unroll
        for (int mt = 0; mt < 2; mt++) {
            int srow = wm * 32 + mt * 16 + qi;
#pragma unroll
            for (int nt = 0; nt < 8; nt++) {
                int h = (wn - 4) * 64 + nt * 8 + 2 * qj;
                T[h * 72 + srow]           = __float2half_rn(c[mt][nt][0]);
                T[(h + 1) * 72 + srow]     = __float2half_rn(c[mt][nt][1]);
                T[h * 72 + srow + 8]       = __float2half_rn(c[mt][nt][2]);
                T[(h + 1) * 72 + srow + 8] = __float2half_rn(c[mt][nt][3]);
            }
        }
    }
    __syncthreads();
    {
        const int b = m0 >> 11, s0 = m0 & 2047;
        if (tid < 256) {
#pragma unroll
            for (int p = 0; p < 8; p++) {
                int i = tid + p * 256;
                int h = i >> 4, cc = i & 15;
                uint2 v = *reinterpret_cast<const uint2*>(&T[h * 72 + cc * 4]);
                *reinterpret_cast<uint2*>(
                    &g_vt[((size_t)b * VTROWS + h) * SEQ + s0 + cc * 4]) = v;
            }
        }
    }
}

// ---------------------------------------------------------------------------
// Kernel B: flash attention (fp16 mma), BN=64, DOUBLE-buffered K and V.
// One combined K+V cp.async group per key tile, issued at end of iter kt into
// the just-drained buffers -> full-iteration landing window. P in registers,
// row-sums via the ones-column (o[16]), exp via ex2.approx.
// ---------------------------------------------------------------------------
#define KS_H (64 * 136)
#define VT_H (144 * 72)
#define FA_SMEM ((2 * KS_H + 2 * VT_H) * 2)   // 76288 B

__global__ __launch_bounds__(128, 2) void flash_mma(float* __restrict__ out)
{
    extern __shared__ __half smf[];
    const unsigned SB = (unsigned)__cvta_generic_to_shared(smf);
    const unsigned KB0 = SB;                       // Ks buffers
    const unsigned VB0 = SB + 2 * KS_H * 2;        // Vt buffers

    const int tid = threadIdx.x;
    const int wid = tid >> 5, lane = tid & 31;
    const int qi = lane >> 2, qj = lane & 3;
    const int g  = lane >> 3, r = lane & 7;
    const int l16 = lane & 15, hi16 = lane >> 4;

    const int bid = blockIdx.x;
    const int t  = (bid < 148) ? bid : 403 - bid;
    const int qt = 31 - (t >> 3);
    const int b  = t & 7;
    const int q0 = qt * 64;
    const int m0 = wid * 16;

    const __half* kbase  = g_k  + (size_t)b * SEQ * HEAD;
    const __half* vtbase = g_vt + (size_t)b * VTROWS * SEQ;

    // ---- stage Q through Ks buf0, ldmatrix into regs ----
    {
        const __half* qb = g_q + ((size_t)b * SEQ + q0) * HEAD;
#pragma unroll
        for (int p = 0; p < 8; p++) {
            int i = tid + p * 128;
            int row = i >> 4, c4 = i & 15;
            cpasync16(KB0 + (unsigned)(row * 272 + c4 * 16), qb + (size_t)row * HEAD + c4 * 8);
        }
        CP_COMMIT; CP_WAIT0;
        __syncthreads();
    }
    unsigned qa[8][4];
    {
        const unsigned aOff = (unsigned)((m0 + l16) * 272 + hi16 * 16);
#pragma unroll
        for (int ks = 0; ks < 8; ks++) ldsm4(qa[ks], KB0 + aOff + ks * 32);
    }
    __syncthreads();   // buf0 free

    // prologue: group0 = K0+V0 into buf0; group1 = K1+V1 into buf1 (guarded)
#pragma unroll
    for (int kt0 = 0; kt0 < 2; kt0++) {
        if (kt0 <= qt) {
            const unsigned KsB = KB0 + kt0 * (KS_H * 2);
            const unsigned VtB = VB0 + kt0 * (VT_H * 2);
            const __half* kb = kbase + (size_t)kt0 * 64 * HEAD;
            const __half* vb = vtbase + (size_t)kt0 * 64;
#pragma unroll
            for (int p = 0; p < 8; p++) {
                int i = tid + p * 128;
                int row = i >> 4, c4 = i & 15;
                cpasync16(KsB + (unsigned)(row * 272 + c4 * 16),
                          kb + (size_t)row * HEAD + c4 * 8);
            }
#pragma unroll
            for (int p = 0; p < 9; p++) {
                int i = tid + p * 128;
                if (i < 1088) {
                    int h = i >> 3, c4 = i & 7;
                    cpasync16(VtB + (unsigned)(h * 144 + c4 * 16),
                              vb + (size_t)h * SEQ + c4 * 8);
                }
            }
        }
        CP_COMMIT;
    }

    // o tiles: 0..15 = HEAD, 16 = l (ones col), 17 = pad (unused)
    float o[18][4];
#pragma unroll
    for (int nt = 0; nt < 18; nt++)
#pragma unroll
        for (int e = 0; e < 4; e++) o[nt][e] = 0.f;
    float mx0 = -INFINITY, mx1 = -INFINITY;

    const int r0g = q0 + m0 + qi;
    const int r1g = r0g + 8;

    const unsigned bOff = (unsigned)(((g >> 1) * 8 + r) * 272 + (g & 1) * 16);
    const unsigned vOff = (unsigned)(((g >> 1) * 8 + r) * 144 + (g & 1) * 16);

    for (int kt = 0; kt <= qt; kt++) {
        CP_WAIT1;            // group kt landed (group kt+1 may still fly)
        __syncthreads();

        const unsigned KsB = KB0 + (kt & 1) * (KS_H * 2);
        const unsigned VtB = VB0 + (kt & 1) * (VT_H * 2);

        // ---- S = Q K^T ----
        float s[8][4];
#pragma unroll
        for (int nt = 0; nt < 8; nt++)
#pragma unroll
            for (int e = 0; e < 4; e++) s[nt][e] = 0.f;
#pragma unroll
        for (int ks = 0; ks < 8; ks++) {
#pragma unroll
            for (int np = 0; np < 4; np++) {
                unsigned bm[4];
                ldsm4(bm, KsB + bOff + (unsigned)(np * 4352 + ks * 32));
                mma_f16(s[2 * np],     qa[ks][0], qa[ks][1], qa[ks][2], qa[ks][3], bm[0], bm[1]);
                mma_f16(s[2 * np + 1], qa[ks][0], qa[ks][1], qa[ks][2], qa[ks][3], bm[2], bm[3]);
            }
        }

        // causal mask on the diagonal tile
        if (kt == qt) {
#pragma unroll
            for (int nt = 0; nt < 8; nt++) {
                int cb = kt * 64 + nt * 8 + 2 * qj;
                if (cb > r0g)     s[nt][0] = -INFINITY;
                if (cb + 1 > r0g) s[nt][1] = -INFINITY;
                if (cb > r1g)     s[nt][2] = -INFINITY;
                if (cb + 1 > r1g) s[nt][3] = -INFINITY;
            }
        }

        // ---- online softmax: P packed into PV A-frag registers ----
        unsigned pp0[8], pp1[8];
        {
            float t0 = -INFINITY, t1 = -INFINITY;
#pragma unroll
            for (int nt = 0; nt < 8; nt++) {
                t0 = fmaxf(t0, fmaxf(s[nt][0], s[nt][1]));
                t1 = fmaxf(t1, fmaxf(s[nt][2], s[nt][3]));
            }
            t0 = fmaxf(t0, __shfl_xor_sync(0xffffffffu, t0, 1));
            t0 = fmaxf(t0, __shfl_xor_sync(0xffffffffu, t0, 2));
            t1 = fmaxf(t1, __shfl_xor_sync(0xffffffffu, t1, 1));
            t1 = fmaxf(t1, __shfl_xor_sync(0xffffffffu, t1, 2));

            float mn0 = fmaxf(mx0, t0), mn1 = fmaxf(mx1, t1);
            float cr0 = ex2f(mx0 - mn0), cr1 = ex2f(mx1 - mn1);
            mx0 = mn0; mx1 = mn1;

#pragma unroll
            for (int nt = 0; nt < 8; nt++) {
                pp0[nt] = packh2(ex2f(s[nt][0] - mn0), ex2f(s[nt][1] - mn0));
                pp1[nt] = packh2(ex2f(s[nt][2] - mn1), ex2f(s[nt][3] - mn1));
            }

            if (__any_sync(0xffffffffu, (cr0 < 1.f) || (cr1 < 1.f))) {
#pragma unroll
                for (int nt = 0; nt < 17; nt++) {
                    o[nt][0] *= cr0; o[nt][1] *= cr0;
                    o[nt][2] *= cr1; o[nt][3] *= cr1;
                }
            }
        }

        // ---- O += P V : A from registers, 4 k16 steps x 9 n-pairs ----
#pragma unroll
        for (int ks = 0; ks < 4; ks++) {
            unsigned a0 = pp0[2 * ks], a1 = pp1[2 * ks];
            unsigned a2 = pp0[2 * ks + 1], a3 = pp1[2 * ks + 1];
#pragma unroll
            for (int np = 0; np < 9; np++) {
                unsigned bm[4];
                ldsm4(bm, VtB + vOff + (unsigned)(np * 2304 + ks * 32));
                mma_f16(o[2 * np],     a0, a1, a2, a3, bm[0], bm[1]);
                mma_f16(o[2 * np + 1], a0, a1, a2, a3, bm[2], bm[3]);
            }
        }
        __syncthreads();     // all warps done with buffers (kt&1)

        // issue K(kt+2)+V(kt+2) into the just-drained buffers
        if (kt + 2 <= qt) {
            const unsigned KsN = KB0 + (kt & 1) * (KS_H * 2);
            const unsigned VtN = VB0 + (kt & 1) * (VT_H * 2);
            const __half* kb = kbase + (size_t)(kt + 2) * 64 * HEAD;
            const __half* vb = vtbase + (size_t)(kt + 2) * 64;
#pragma unroll
            for (int p = 0; p < 8; p++) {
                int i = tid + p * 128;
                int row = i >> 4, c4 = i & 15;
                cpasync16(KsN + (unsigned)(row * 272 + c4 * 16),
                          kb + (size_t)row * HEAD + c4 * 8);
            }
#pragma unroll
            for (int p = 0; p < 9; p++) {
                int i = tid + p * 128;
                if (i < 1088) {
                    int h = i >> 3, c4 = i & 7;
                    cpasync16(VtN + (unsigned)(h * 144 + c4 * 16),
                              vb + (size_t)h * SEQ + c4 * 8);
                }
            }
        }
        CP_COMMIT;           // unconditional: keeps group arithmetic
    }

    // epilogue: l lives in o[16][0]/o[16][2] of the qj==0 lane of each quad
    {
        float l0 = __shfl_sync(0xffffffffu, o[16][0], lane & 28);
        float l1 = __shfl_sync(0xffffffffu, o[16][2], lane & 28);
        float inv0 = 1.f / l0, inv1 = 1.f / l1;
        float* ob = out + ((size_t)b * SEQ) * HEAD;
#pragma unroll
        for (int nt = 0; nt < 16; nt++) {
            int col = nt * 8 + 2 * qj;
            *reinterpret_cast<float2*>(&ob[(size_t)r0g * HEAD + col]) =
                make_float2(o[nt][0] * inv0, o[nt][1] * inv0);
            *reinterpret_cast<float2*>(&ob[(size_t)r1g * HEAD + col]) =
                make_float2(o[nt][2] * inv1, o[nt][3] * inv1);
        }
    }
}

// ---------------------------------------------------------------------------
extern "C" void kernel_launch(void* const* d_in, const int* in_sizes, int n_in,
                              void* d_out, int out_size)
{
    const float* x  = (const float*)d_in[0];
    const float* Wk = (const float*)d_in[1];
    const float* Wq = (const float*)d_in[2];
    const float* Wv = (const float*)d_in[3];
    float* out = (float*)d_out;

    w_prep<<<dim3(HEAD, 3), 256>>>(Wq, Wk, Wv);
    vt_ones<<<128, 256>>>();

    cudaFuncSetAttribute(qkv_fused, cudaFuncAttributeMaxDynamicSharedMemorySize, QKV_SMEM);
    qkv_fused<<<MTOT / 64, 384, QKV_SMEM>>>(x);

    cudaFuncSetAttribute(flash_mma, cudaFuncAttributeMaxDynamicSharedMemorySize, FA_SMEM);
    flash_mma<<<dim3(256, 1), 128, FA_SMEM>>>(out);
}

// round 15
// speedup vs baseline: 1.1650x; 1.0358x over previous
#include <cuda_runtime.h>
#include <cuda_fp16.h>
#include <math.h>

#define EMBED 1024
#define HEAD  128
#define BATCH 8
#define SEQ   2048
#define MTOT  (BATCH*SEQ)
#define VTROWS 136                      // 128 V rows + ones row + 7 zero rows

#define QK_SCALE 0.045084295033136845f  // log2(e) / sqrt(1024)

// Scratch (allocation-free). fp16 activations, fp32 split-K partials.
__device__ __half g_q[MTOT * HEAD];             // pre-scaled by log2(e)/32
__device__ __half g_k[MTOT * HEAD];
__device__ __half g_vt[BATCH * VTROWS * SEQ];   // V^T: [b][h][s], h=128 ones
__device__ __half g_wt[3][HEAD][EMBED];         // W^T fp16: [z][n][k]
__device__ float  g_pO[2][MTOT * HEAD];         // split-K partial O (unnormalized)
__device__ float2 g_pML[2][MTOT];               // split-K partial (m, l)

// ---------------------------------------------------------------------------
// helpers
// ---------------------------------------------------------------------------
__device__ __forceinline__ unsigned packh2(float a, float b) {
    __half2 h = __floats2half2_rn(a, b);
    return *reinterpret_cast<unsigned*>(&h);
}
__device__ __forceinline__ float ex2f(float x) {
    float y; asm("ex2.approx.f32 %0, %1;" : "=f"(y) : "f"(x)); return y;
}
__device__ __forceinline__ void mma_f16(float d[4],
                                        unsigned a0, unsigned a1, unsigned a2, unsigned a3,
                                        unsigned b0, unsigned b1) {
    asm volatile(
        "mma.sync.aligned.m16n8k16.row.col.f32.f16.f16.f32 "
        "{%0,%1,%2,%3}, {%4,%5,%6,%7}, {%8,%9}, {%0,%1,%2,%3};"
        : "+f"(d[0]), "+f"(d[1]), "+f"(d[2]), "+f"(d[3])
        : "r"(a0), "r"(a1), "r"(a2), "r"(a3), "r"(b0), "r"(b1));
}
__device__ __forceinline__ void ldsm4(unsigned m[4], unsigned saddr) {
    asm volatile("ldmatrix.sync.aligned.m8n8.x4.shared.b16 {%0,%1,%2,%3}, [%4];"
                 : "=r"(m[0]), "=r"(m[1]), "=r"(m[2]), "=r"(m[3]) : "r"(saddr));
}
__device__ __forceinline__ void cpasync16(unsigned dst, const void* src) {
    asm volatile("cp.async.ca.shared.global [%0], [%1], 16;" :: "r"(dst), "l"(src));
}
#define CP_COMMIT asm volatile("cp.async.commit_group;")
#define CP_WAIT0  asm volatile("cp.async.wait_group 0;" ::: "memory")
#define CP_WAIT1  asm volatile("cp.async.wait_group 1;" ::: "memory")

// ---------------------------------------------------------------------------
// Prep 1: transpose + fp16 round of W into g_wt[z][n][k].
// ---------------------------------------------------------------------------
__global__ __launch_bounds__(256) void w_prep(const float* __restrict__ Wq,
                                              const float* __restrict__ Wk,
                                              const float* __restrict__ Wv)
{
    const int z = blockIdx.y;
    const float* W = (z == 0) ? Wq : (z == 1) ? Wk : Wv;
    const int n = blockIdx.x;
    const int k = threadIdx.x * 4;
    float a = W[(size_t)(k + 0) * HEAD + n];
    float b = W[(size_t)(k + 1) * HEAD + n];
    float c = W[(size_t)(k + 2) * HEAD + n];
    float d = W[(size_t)(k + 3) * HEAD + n];
    *reinterpret_cast<uint2*>(&g_wt[z][n][k]) =
        make_uint2(packh2(a, b), packh2(c, d));
}

// ---------------------------------------------------------------------------
// Prep 2: fill g_vt rows 128..135 (ones row + zero pad).
// ---------------------------------------------------------------------------
__global__ __launch_bounds__(256) void vt_ones()
{
    int j = blockIdx.x * 256 + threadIdx.x;
    int b = j >> 12;
    int rem = j & 4095;
    int hh = rem >> 9;
    int s4 = (rem & 511) * 4;
    unsigned v = (hh == 0) ? packh2(1.f, 1.f) : 0u;
    *reinterpret_cast<uint2*>(
        &g_vt[((size_t)b * VTROWS + 128 + hh) * SEQ + s4]) = make_uint2(v, v);
}

// ---------------------------------------------------------------------------
// Kernel A: FUSED QKV projection (fp16 mma), triple-buffered, K-chunk 64.
// CTA = 64 rows x 384 cols (Q|K|V), 384 threads = 12 warps (2m x 6n),
// warp tile m32 x n64, 4 k16-steps per chunk. Strides 72 halves (144B).
// ---------------------------------------------------------------------------
#define FXS_H (64 * 72)      // 4608 halves per X buffer
#define FWS_H (384 * 72)     // 27648 halves per W buffer
#define BUFH  (FXS_H + FWS_H)
#define QKV_SMEM (3 * BUFH * 2)   // 193536 B (dynamic)

__global__ __launch_bounds__(384, 1) void qkv_fused(const float* __restrict__ x)
{
    extern __shared__ __half smh[];

    const int tid = threadIdx.x;
    const int wid = tid >> 5, lane = tid & 31;
    const int qi = lane >> 2, qj = lane & 3;
    const int g  = lane >> 3, r = lane & 7;
    const int l16 = lane & 15, hi16 = lane >> 4;
    const int wn = wid % 6, wm = wid / 6;
    const int m0 = blockIdx.x * 64;

    const unsigned SB = (unsigned)__cvta_generic_to_shared(smh);
    const __half* wsrc = &g_wt[0][0][0];    // flat rows: z*128 + n

    float c[2][8][4];
#pragma unroll
    for (int mt = 0; mt < 2; mt++)
#pragma unroll
        for (int nt = 0; nt < 8; nt++)
#pragma unroll
            for (int e = 0; e < 4; e++) c[mt][nt][e] = 0.f;

    const float* xbase = x + (size_t)m0 * EMBED;

    // prologue: chunks 0,1 (W via cp.async groups; X direct LDG+cvt+STS)
#pragma unroll
    for (int b2 = 0; b2 < 2; b2++) {
        const unsigned WsB = SB + (unsigned)(b2 * BUFH + FXS_H) * 2;
        const int k0 = b2 * 64;
#pragma unroll
        for (int p = 0; p < 8; p++) {
            int u = tid + p * 384;
            int n = u >> 3, i = u & 7;
            cpasync16(WsB + (unsigned)(n * 144 + i * 16),
                      wsrc + (size_t)n * EMBED + k0 + i * 8);
        }
        CP_COMMIT;
#pragma unroll
        for (int p = 0; p < 2; p++) {
            int u = tid + p * 384;
            if (u < 512) {
                int row = u >> 3, i = u & 7;
                const float4* s = reinterpret_cast<const float4*>(
                    xbase + (size_t)row * EMBED + k0 + i * 8);
                float4 v0 = s[0], v1 = s[1];
                *reinterpret_cast<uint4*>(&smh[b2 * BUFH + row * 72 + i * 8]) =
                    make_uint4(packh2(v0.x, v0.y), packh2(v0.z, v0.w),
                               packh2(v1.x, v1.y), packh2(v1.z, v1.w));
            }
        }
    }

    for (int ch = 0; ch < 16; ch++) {
        const int cur = ch % 3;
        CP_WAIT1;            // W(ch) landed (W(ch+1) may still fly)
        __syncthreads();     // mma(ch-1) done by all warps -> buf (ch+2)%3 free

        float4 xa[2], xb2[2];
        const bool hx = (ch + 2 < 16);
        const int nb = (ch + 2) % 3;
        if (hx) {
            const int k0n = (ch + 2) * 64;
            const unsigned WsB = SB + (unsigned)(nb * BUFH + FXS_H) * 2;
#pragma unroll
            for (int p = 0; p < 8; p++) {
                int u = tid + p * 384;
                int n = u >> 3, i = u & 7;
                cpasync16(WsB + (unsigned)(n * 144 + i * 16),
                          wsrc + (size_t)n * EMBED + k0n + i * 8);
            }
#pragma unroll
            for (int p = 0; p < 2; p++) {
                int u = tid + p * 384;
                if (u < 512) {
                    int row = u >> 3, i = u & 7;
                    const float4* s = reinterpret_cast<const float4*>(
                        xbase + (size_t)row * EMBED + k0n + i * 8);
                    xa[p] = s[0]; xb2[p] = s[1];
                }
            }
        }
        CP_COMMIT;           // unconditional: keeps group arithmetic

        // compute on buffer cur: 4 k16 steps
        const unsigned XsB = SB + (unsigned)(cur * BUFH) * 2;
        const unsigned WsB = XsB + (unsigned)FXS_H * 2;
#pragma unroll
        for (int ks = 0; ks < 4; ks++) {
            unsigned a[2][4];
#pragma unroll
            for (int mt = 0; mt < 2; mt++)
                ldsm4(a[mt], XsB + (unsigned)((wm * 32 + mt * 16 + l16) * 144
                                              + hi16 * 16 + ks * 32));
#pragma unroll
            for (int np = 0; np < 4; np++) {
                unsigned bm[4];
                ldsm4(bm, WsB + (unsigned)((wn * 64 + np * 16 + (g >> 1) * 8 + r) * 144
                                           + (g & 1) * 16 + ks * 32));
                mma_f16(c[0][2 * np],     a[0][0], a[0][1], a[0][2], a[0][3], bm[0], bm[1]);
                mma_f16(c[0][2 * np + 1], a[0][0], a[0][1], a[0][2], a[0][3], bm[2], bm[3]);
                mma_f16(c[1][2 * np],     a[1][0], a[1][1], a[1][2], a[1][3], bm[0], bm[1]);
                mma_f16(c[1][2 * np + 1], a[1][0], a[1][1], a[1][2], a[1][3], bm[2], bm[3]);
            }
        }

        if (hx) {
#pragma unroll
            for (int p = 0; p < 2; p++) {
                int u = tid + p * 384;
                if (u < 512) {
                    int row = u >> 3, i = u & 7;
                    *reinterpret_cast<uint4*>(&smh[nb * BUFH + row * 72 + i * 8]) =
                        make_uint4(packh2(xa[p].x, xa[p].y), packh2(xa[p].z, xa[p].w),
                                   packh2(xb2[p].x, xb2[p].y), packh2(xb2[p].z, xb2[p].w));
                }
            }
        }
    }

    // ---- epilogue (as R14; T stride 72) ----
    if (wn < 4) {
        __half* out = (wn < 2) ? g_q : g_k;
        const float sc = (wn < 2) ? QK_SCALE : 1.0f;
        const int cb = (wn & 1) * 64;
#pragma unroll
        for (int mt = 0; mt < 2; mt++) {
            int r0 = m0 + wm * 32 + mt * 16 + qi;
#pragma unroll
            for (int nt = 0; nt < 8; nt++) {
                int col = cb + nt * 8 + 2 * qj;
                *reinterpret_cast<unsigned*>(&out[(size_t)r0 * HEAD + col]) =
                    packh2(c[mt][nt][0] * sc, c[mt][nt][1] * sc);
                *reinterpret_cast<unsigned*>(&out[(size_t)(r0 + 8) * HEAD + col]) =
                    packh2(c[mt][nt][2] * sc, c[mt][nt][3] * sc);
            }
        }
    }
    __syncthreads();
    __half* T = smh;                 // [h=128][s=64], stride 72 halves
    if (wn >= 4) {
#pragma unroll
        for (int mt = 0; mt < 2; mt++) {
            int srow = wm * 32 + mt * 16 + qi;
#pragma unroll
            for (int nt = 0; nt < 8; nt++) {
                int h = (wn - 4) * 64 + nt * 8 + 2 * qj;
                T[h * 72 + srow]           = __float2half_rn(c[mt][nt][0]);
                T[(h + 1) * 72 + srow]     = __float2half_rn(c[mt][nt][1]);
                T[h * 72 + srow + 8]       = __float2half_rn(c[mt][nt][2]);
                T[(h + 1) * 72 + srow + 8] = __float2half_rn(c[mt][nt][3]);
            }
        }
    }
    __syncthreads();
    {
        const int b = m0 >> 11, s0 = m0 & 2047;
        if (tid < 256) {
#pragma unroll
            for (int p = 0; p < 8; p++) {
                int i = tid + p * 256;
                int h = i >> 4, cc = i & 15;
                uint2 v = *reinterpret_cast<const uint2*>(&T[h * 72 + cc * 4]);
                *reinterpret_cast<uint2*>(
                    &g_vt[((size_t)b * VTROWS + h) * SEQ + s0 + cc * 4]) = v;
            }
        }
    }
}

// ---------------------------------------------------------------------------
// Kernel B: flash attention (fp16 mma), split-K for qt>=16.
// grid 384: gid<256 -> split CTAs (qt 31..16, lo/hi key halves, partials);
// gid>=256 -> unsplit (qt 15..0, direct output). Double-buffered K+V.
// ---------------------------------------------------------------------------
#define KS_H (64 * 136)
#define VT_H (144 * 72)
#define FA_SMEM ((2 * KS_H + 2 * VT_H) * 2)   // 76288 B

__global__ __launch_bounds__(128, 2) void flash_mma(float* __restrict__ out)
{
    extern __shared__ __half smf[];
    const unsigned SB = (unsigned)__cvta_generic_to_shared(smf);
    const unsigned KB0 = SB;
    const unsigned VB0 = SB + 2 * KS_H * 2;

    const int tid = threadIdx.x;
    const int wid = tid >> 5, lane = tid & 31;
    const int qi = lane >> 2, qj = lane & 3;
    const int g  = lane >> 3, r = lane & 7;
    const int l16 = lane & 15, hi16 = lane >> 4;

    // work mapping
    const int gid = blockIdx.x;
    int qt, b, kt0, kt1, half;
    bool partial;
    if (gid < 256) {
        partial = true;
        qt = 31 - (gid >> 4);
        b  = (gid >> 1) & 7;
        half = gid & 1;
        int h0 = (qt + 2) >> 1;
        kt0 = half ? h0 : 0;
        kt1 = half ? (qt + 1) : h0;
    } else {
        partial = false;
        int v = gid - 256;
        qt = 15 - (v >> 3);
        b  = v & 7;
        half = 0;
        kt0 = 0;
        kt1 = qt + 1;
    }
    const int nkt = kt1 - kt0;          // >= 1 always
    const int q0 = qt * 64;
    const int m0 = wid * 16;

    const __half* kbase  = g_k  + (size_t)b * SEQ * HEAD;
    const __half* vtbase = g_vt + (size_t)b * VTROWS * SEQ;

    // ---- stage Q through Ks buf0, ldmatrix into regs ----
    {
        const __half* qb = g_q + ((size_t)b * SEQ + q0) * HEAD;
#pragma unroll
        for (int p = 0; p < 8; p++) {
            int i = tid + p * 128;
            int row = i >> 4, c4 = i & 15;
            cpasync16(KB0 + (unsigned)(row * 272 + c4 * 16), qb + (size_t)row * HEAD + c4 * 8);
        }
        CP_COMMIT; CP_WAIT0;
        __syncthreads();
    }
    unsigned qa[8][4];
    {
        const unsigned aOff = (unsigned)((m0 + l16) * 272 + hi16 * 16);
#pragma unroll
        for (int ks = 0; ks < 8; ks++) ldsm4(qa[ks], KB0 + aOff + ks * 32);
    }
    __syncthreads();   // buf0 free

    // prologue: groups for it=0,1 (K+V each); empty commit keeps arithmetic
#pragma unroll
    for (int it0 = 0; it0 < 2; it0++) {
        if (it0 < nkt) {
            const int kt = kt0 + it0;
            const unsigned KsB = KB0 + it0 * (KS_H * 2);
            const unsigned VtB = VB0 + it0 * (VT_H * 2);
            const __half* kb = kbase + (size_t)kt * 64 * HEAD;
            const __half* vb = vtbase + (size_t)kt * 64;
#pragma unroll
            for (int p = 0; p < 8; p++) {
                int i = tid + p * 128;
                int row = i >> 4, c4 = i & 15;
                cpasync16(KsB + (unsigned)(row * 272 + c4 * 16),
                          kb + (size_t)row * HEAD + c4 * 8);
            }
#pragma unroll
            for (int p = 0; p < 9; p++) {
                int i = tid + p * 128;
                if (i < 1088) {
                    int h = i >> 3, c4 = i & 7;
                    cpasync16(VtB + (unsigned)(h * 144 + c4 * 16),
                              vb + (size_t)h * SEQ + c4 * 8);
                }
            }
        }
        CP_COMMIT;
    }

    // o tiles: 0..15 = HEAD, 16 = l (ones col), 17 = pad (unused)
    float o[18][4];
#pragma unroll
    for (int nt = 0; nt < 18; nt++)
#pragma unroll
        for (int e = 0; e < 4; e++) o[nt][e] = 0.f;
    float mx0 = -INFINITY, mx1 = -INFINITY;

    const int r0g = q0 + m0 + qi;
    const int r1g = r0g + 8;

    const unsigned bOff = (unsigned)(((g >> 1) * 8 + r) * 272 + (g & 1) * 16);
    const unsigned vOff = (unsigned)(((g >> 1) * 8 + r) * 144 + (g & 1) * 16);

    for (int it = 0; it < nkt; it++) {
        const int kt = kt0 + it;
        CP_WAIT1;            // group it landed (group it+1 may still fly)
        __syncthreads();

        const unsigned KsB = KB0 + (it & 1) * (KS_H * 2);
        const unsigned VtB = VB0 + (it & 1) * (VT_H * 2);

        // ---- S = Q K^T ----
        float s[8][4];
#pragma unroll
        for (int nt = 0; nt < 8; nt++)
#pragma unroll
            for (int e = 0; e < 4; e++) s[nt][e] = 0.f;
#pragma unroll
        for (int ks = 0; ks < 8; ks++) {
#pragma unroll
            for (int np = 0; np < 4; np++) {
                unsigned bm[4];
                ldsm4(bm, KsB + bOff + (unsigned)(np * 4352 + ks * 32));
                mma_f16(s[2 * np],     qa[ks][0], qa[ks][1], qa[ks][2], qa[ks][3], bm[0], bm[1]);
                mma_f16(s[2 * np + 1], qa[ks][0], qa[ks][1], qa[ks][2], qa[ks][3], bm[2], bm[3]);
            }
        }

        // causal mask on the diagonal tile
        if (kt == qt) {
#pragma unroll
            for (int nt = 0; nt < 8; nt++) {
                int cb = kt * 64 + nt * 8 + 2 * qj;
                if (cb > r0g)     s[nt][0] = -INFINITY;
                if (cb + 1 > r0g) s[nt][1] = -INFINITY;
                if (cb > r1g)     s[nt][2] = -INFINITY;
                if (cb + 1 > r1g) s[nt][3] = -INFINITY;
            }
        }

        // ---- online softmax: P packed into PV A-frag registers ----
        unsigned pp0[8], pp1[8];
        {
            float t0 = -INFINITY, t1 = -INFINITY;
#pragma unroll
            for (int nt = 0; nt < 8; nt++) {
                t0 = fmaxf(t0, fmaxf(s[nt][0], s[nt][1]));
                t1 = fmaxf(t1, fmaxf(s[nt][2], s[nt][3]));
            }
            t0 = fmaxf(t0, __shfl_xor_sync(0xffffffffu, t0, 1));
            t0 = fmaxf(t0, __shfl_xor_sync(0xffffffffu, t0, 2));
            t1 = fmaxf(t1, __shfl_xor_sync(0xffffffffu, t1, 1));
            t1 = fmaxf(t1, __shfl_xor_sync(0xffffffffu, t1, 2));

            float mn0 = fmaxf(mx0, t0), mn1 = fmaxf(mx1, t1);
            float cr0 = ex2f(mx0 - mn0), cr1 = ex2f(mx1 - mn1);
            mx0 = mn0; mx1 = mn1;

#pragma unroll
            for (int nt = 0; nt < 8; nt++) {
                pp0[nt] = packh2(ex2f(s[nt][0] - mn0), ex2f(s[nt][1] - mn0));
                pp1[nt] = packh2(ex2f(s[nt][2] - mn1), ex2f(s[nt][3] - mn1));
            }

            if (__any_sync(0xffffffffu, (cr0 < 1.f) || (cr1 < 1.f))) {
#pragma unroll
                for (int nt = 0; nt < 17; nt++) {
                    o[nt][0] *= cr0; o[nt][1] *= cr0;
                    o[nt][2] *= cr1; o[nt][3] *= cr1;
                }
            }
        }

        // ---- O += P V : A from registers, 4 k16 steps x 9 n-pairs ----
#pragma unroll
        for (int ks = 0; ks < 4; ks++) {
            unsigned a0 = pp0[2 * ks], a1 = pp1[2 * ks];
            unsigned a2 = pp0[2 * ks + 1], a3 = pp1[2 * ks + 1];
#pragma unroll
            for (int np = 0; np < 9; np++) {
                unsigned bm[4];
                ldsm4(bm, VtB + vOff + (unsigned)(np * 2304 + ks * 32));
                mma_f16(o[2 * np],     a0, a1, a2, a3, bm[0], bm[1]);
                mma_f16(o[2 * np + 1], a0, a1, a2, a3, bm[2], bm[3]);
            }
        }
        __syncthreads();     // all warps done with buffers (it&1)

        // issue K/V for it+2 into the just-drained buffers
        if (it + 2 < nkt) {
            const int ktn = kt0 + it + 2;
            const unsigned KsN = KB0 + (it & 1) * (KS_H * 2);
            const unsigned VtN = VB0 + (it & 1) * (VT_H * 2);
            const __half* kb = kbase + (size_t)ktn * 64 * HEAD;
            const __half* vb = vtbase + (size_t)ktn * 64;
#pragma unroll
            for (int p = 0; p < 8; p++) {
                int i = tid + p * 128;
                int row = i >> 4, c4 = i & 15;
                cpasync16(KsN + (unsigned)(row * 272 + c4 * 16),
                          kb + (size_t)row * HEAD + c4 * 8);
            }
#pragma unroll
            for (int p = 0; p < 9; p++) {
                int i = tid + p * 128;
                if (i < 1088) {
                    int h = i >> 3, c4 = i & 7;
                    cpasync16(VtN + (unsigned)(h * 144 + c4 * 16),
                              vb + (size_t)h * SEQ + c4 * 8);
                }
            }
        }
        CP_COMMIT;           // unconditional: keeps group arithmetic
    }

    // ---- epilogue ----
    if (!partial) {
        float l0 = __shfl_sync(0xffffffffu, o[16][0], lane & 28);
        float l1 = __shfl_sync(0xffffffffu, o[16][2], lane & 28);
        float inv0 = 1.f / l0, inv1 = 1.f / l1;
        float* ob = out + ((size_t)b * SEQ) * HEAD;
#pragma unroll
        for (int nt = 0; nt < 16; nt++) {
            int col = nt * 8 + 2 * qj;
            *reinterpret_cast<float2*>(&ob[(size_t)r0g * HEAD + col]) =
                make_float2(o[nt][0] * inv0, o[nt][1] * inv0);
            *reinterpret_cast<float2*>(&ob[(size_t)r1g * HEAD + col]) =
                make_float2(o[nt][2] * inv1, o[nt][3] * inv1);
        }
    } else {
        float* pb = g_pO[half] + ((size_t)b * SEQ) * HEAD;
#pragma unroll
        for (int nt = 0; nt < 16; nt++) {
            int col = nt * 8 + 2 * qj;
            *reinterpret_cast<float2*>(&pb[(size_t)r0g * HEAD + col]) =
                make_float2(o[nt][0], o[nt][1]);
            *reinterpret_cast<float2*>(&pb[(size_t)r1g * HEAD + col]) =
                make_float2(o[nt][2], o[nt][3]);
        }
        if (qj == 0) {
            g_pML[half][(size_t)b * SEQ + r0g] = make_float2(mx0, o[16][0]);
            g_pML[half][(size_t)b * SEQ + r1g] = make_float2(mx1, o[16][2]);
        }
    }
}

// ---------------------------------------------------------------------------
// Kernel C: split-K merge for rows with qt>=16 (row_in_batch >= 1024).
// out = (O0*w0 + O1*w1) / (l0*w0 + l1*w1),  wi = 2^(mi - m*).
// grid 1024 x 256: thread = (row, 4-col group).
// ---------------------------------------------------------------------------
__global__ __launch_bounds__(256) void flash_merge(float* __restrict__ out)
{
    int idx = blockIdx.x * 256 + threadIdx.x;       // 0..262143
    int row_local = idx >> 5;                       // 0..8191
    int b = row_local >> 10, rin = row_local & 1023;
    size_t grow = (size_t)b * SEQ + 1024 + rin;
    int cg = (idx & 31) * 4;

    float2 ml0 = g_pML[0][grow], ml1 = g_pML[1][grow];
    float mstar = fmaxf(ml0.x, ml1.x);
    float w0 = ex2f(ml0.x - mstar), w1 = ex2f(ml1.x - mstar);
    float linv = 1.f / (ml0.y * w0 + ml1.y * w1);

    float4 a = *reinterpret_cast<const float4*>(&g_pO[0][grow * HEAD + cg]);
    float4 c = *reinterpret_cast<const float4*>(&g_pO[1][grow * HEAD + cg]);
    float4 o;
    o.x = (a.x * w0 + c.x * w1) * linv;
    o.y = (a.y * w0 + c.y * w1) * linv;
    o.z = (a.z * w0 + c.z * w1) * linv;
    o.w = (a.w * w0 + c.w * w1) * linv;
    *reinterpret_cast<float4*>(&out[grow * HEAD + cg]) = o;
}

// ---------------------------------------------------------------------------
extern "C" void kernel_launch(void* const* d_in, const int* in_sizes, int n_in,
                              void* d_out, int out_size)
{
    const float* x  = (const float*)d_in[0];
    const float* Wk = (const float*)d_in[1];
    const float* Wq = (const float*)d_in[2];
    const float* Wv = (const float*)d_in[3];
    float* out = (float*)d_out;

    w_prep<<<dim3(HEAD, 3), 256>>>(Wq, Wk, Wv);
    vt_ones<<<128, 256>>>();

    cudaFuncSetAttribute(qkv_fused, cudaFuncAttributeMaxDynamicSharedMemorySize, QKV_SMEM);
    qkv_fused<<<MTOT / 64, 384, QKV_SMEM>>>(x);

    cudaFuncSetAttribute(flash_mma, cudaFuncAttributeMaxDynamicSharedMemorySize, FA_SMEM);
    flash_mma<<<dim3(384, 1), 128, FA_SMEM>>>(out);

    flash_merge<<<1024, 256>>>(out);
}